// round 5
// baseline (speedup 1.0000x reference)
#include <cuda_runtime.h>
#include <math.h>

#define HID     1024
#define BATCH   32
#define NLAYERS 3
#define NOUT    2500
#define NG      50
#define MODES   32
#define GATES   (3*HID)

#define KSPLIT  4
#define KSEG    (HID/KSPLIT)      // 256 k per segment
#define SEGPAIR (KSEG/2)          // 128 pair-rows per segment
#define RPB     64                // rows per block
#define JW      8                 // rows per warp (8 warps * 8 = 64)
#define ROWS_GRU (2*GATES)        // 6144

typedef unsigned long long ull;

// Activation layout: k-pair interleaved. Feature k, batch b at
//   addr = (k>>1)*64 + 2*b + (k&1)   (pair-row = 64 floats = 256B)
__device__ float g_h[2][NLAYERS][HID * BATCH];
__device__ float g_x[HID * BATCH];
__device__ float g_ct[NG];
__device__ float g_st[NG];
__device__ float g_pg[KSPLIT * ROWS_GRU * BATCH];   // GRU gate partials
__device__ float g_pf[KSPLIT * NOUT * BATCH];       // FC partials

// ---------------- packed fp32x2 fma ----------------
__device__ __forceinline__ void ffma2(ull& acc, ull w, ull xh) {
    asm volatile("fma.rn.f32x2 %0, %1, %2, %0;" : "+l"(acc) : "l"(w), "l"(xh));
}
__device__ __forceinline__ float hsum2(ull v) {
    float2 f = *reinterpret_cast<float2*>(&v);
    return f.x + f.y;
}
union F4U2 { float4 f4; ulonglong2 u2; };

// ---------------- cp.async helpers ----------------
__device__ __forceinline__ void cp16(void* dst, const void* src) {
    unsigned d = (unsigned)__cvta_generic_to_shared(dst);
    asm volatile("cp.async.cg.shared.global [%0], [%1], 16;\n" :: "r"(d), "l"(src));
}
__device__ __forceinline__ void cp_commit() { asm volatile("cp.async.commit_group;\n"); }
template<int N> __device__ __forceinline__ void cp_wait() {
    asm volatile("cp.async.wait_group %0;\n" :: "n"(N));
}

// ---------------- init ----------------
__global__ void init_kernel(const float* __restrict__ x) {
    int tid = blockIdx.x * blockDim.x + threadIdx.x;
    int stride = gridDim.x * blockDim.x;
    float* h = (float*)g_h;
    int total = 2 * NLAYERS * HID * BATCH;
    for (int i = tid; i < total; i += stride) h[i] = 0.0f;
    for (int i = tid; i < HID * BATCH; i += stride) {
        int j = i >> 5, b = i & 31;
        g_x[(j >> 1) * 64 + 2 * b + (j & 1)] = x[b * HID + j];
    }
    if (tid < NG) {
        float ang = 6.283185307179586f * (float)tid / (float)NG;
        g_ct[tid] = cosf(ang);
        g_st[tid] = sinf(ang);
    }
}

// ---------------- partial GEMM ----------------
// P[s][r][b] = sum_{k in seg s} W[r][k] * act[k][b]
// Rows [0, rows_split) use (WA, actA); rows [rows_split, rows_total) use (WB, actB).
// grid.x = ceil(rows_total/RPB) * KSPLIT. block = 256 (8 warps x JW rows).
// Weights: warp-uniform LDG.128 (L2-resident). Acts: K-seg staged in SMEM once.
__global__ __launch_bounds__(256) void gemm_partial_kernel(
    const float* __restrict__ WA, const float* __restrict__ WB,
    const float* __restrict__ actA, const float* __restrict__ actB,
    int rows_split, int rows_total, float* __restrict__ P)
{
    __shared__ __align__(16) float2 Sp[SEGPAIR][BATCH];   // 32 KB

    const int tid  = threadIdx.x;
    const int warp = tid >> 5;
    const int lane = tid & 31;
    const int rb = blockIdx.x / KSPLIT;
    const int ks = blockIdx.x % KSPLIT;
    const int r0 = rb * RPB;

    const float* W;
    const float* act;
    int wrow0, wmax;
    if (r0 < rows_split) { W = WA; act = actA; wrow0 = r0;              wmax = rows_split - 1; }
    else                 { W = WB; act = actB; wrow0 = r0 - rows_split; wmax = rows_total - rows_split - 1; }

    // stage activation K-segment: 128 pair-rows x 256B
    {
        const float* src = act + (size_t)(ks * SEGPAIR) * 64;
        #pragma unroll
        for (int it = 0; it < 8; ++it) {
            int i = tid + it * 256;
            int row = i >> 4, seg = i & 15;
            cp16((float*)&Sp[row][0] + seg * 4, src + (size_t)row * 64 + seg * 4);
        }
        cp_commit(); cp_wait<0>();
    }
    __syncthreads();

    const float* wb[JW];
    #pragma unroll
    for (int i = 0; i < JW; ++i) {
        int wr = wrow0 + warp * JW + i;
        if (wr > wmax) wr = wmax;
        wb[i] = W + (size_t)wr * HID + ks * KSEG;
    }

    ull a[JW];
    #pragma unroll
    for (int i = 0; i < JW; ++i) a[i] = 0;

    #pragma unroll 2
    for (int k8 = 0; k8 < KSEG / 8; ++k8) {
        #pragma unroll
        for (int u = 0; u < 2; ++u) {
            int pr = k8 * 4 + u * 2;
            ull xv0 = *(const ull*)&Sp[pr + 0][lane];
            ull xv1 = *(const ull*)&Sp[pr + 1][lane];
            int ko = k8 * 8 + u * 4;
            #pragma unroll
            for (int i = 0; i < JW; ++i) {
                F4U2 wv; wv.f4 = *(const float4*)(wb[i] + ko);
                ffma2(a[i], wv.u2.x, xv0);
                ffma2(a[i], wv.u2.y, xv1);
            }
        }
    }

    #pragma unroll
    for (int i = 0; i < JW; ++i) {
        int r = r0 + warp * JW + i;
        if (r < rows_total)
            P[((size_t)ks * rows_total + r) * BATCH + lane] = hsum2(a[i]);
    }
}

// ---------------- GRU combine: K-reduce partials + nonlinearity ----------------
// grid = 128, block = 256: thread -> (j = blockIdx.x*8 + warp, b = lane)
__global__ __launch_bounds__(256) void combine_gru_kernel(
    const float* __restrict__ P,
    const float* __restrict__ bih, const float* __restrict__ bhh,
    const float* __restrict__ hT, float* __restrict__ hnT)
{
    const int tid  = threadIdx.x;
    const int lane = tid & 31;
    const int j    = blockIdx.x * 8 + (tid >> 5);

    float air = 0.f, aiz = 0.f, ain = 0.f, ahr = 0.f, ahz = 0.f, ahn = 0.f;
    #pragma unroll
    for (int s = 0; s < KSPLIT; ++s) {
        const float* Ps = P + (size_t)s * ROWS_GRU * BATCH;
        air += Ps[((size_t)(0 * HID + j)) * BATCH + lane];
        aiz += Ps[((size_t)(1 * HID + j)) * BATCH + lane];
        ain += Ps[((size_t)(2 * HID + j)) * BATCH + lane];
        ahr += Ps[((size_t)(GATES + 0 * HID + j)) * BATCH + lane];
        ahz += Ps[((size_t)(GATES + 1 * HID + j)) * BATCH + lane];
        ahn += Ps[((size_t)(GATES + 2 * HID + j)) * BATCH + lane];
    }

    float ir  = air + bih[j];
    float iz  = aiz + bih[HID + j];
    float inn = ain + bih[2 * HID + j];
    float hr  = ahr + bhh[j];
    float hz  = ahz + bhh[HID + j];
    float hn  = ahn + bhh[2 * HID + j];
    float r = 1.0f / (1.0f + __expf(-(ir + hr)));
    float z = 1.0f / (1.0f + __expf(-(iz + hz)));
    float n = tanhf(inn + r * hn);
    const size_t addr = (size_t)(j >> 1) * 64 + 2 * lane + (j & 1);
    float hp = hT[addr];
    hnT[addr] = (1.0f - z) * n + z * hp;
}

// ---------------- FC combine: K-reduce + bias ----------------
// grid = ceil(NOUT/8), block = 256: thread -> (n = blockIdx.x*8 + warp, b = lane)
__global__ __launch_bounds__(256) void combine_fc_kernel(
    const float* __restrict__ P, const float* __restrict__ fcb,
    float* __restrict__ out)
{
    const int tid  = threadIdx.x;
    const int lane = tid & 31;
    const int n    = blockIdx.x * 8 + (tid >> 5);
    if (n >= NOUT) return;

    float acc = fcb[n];
    #pragma unroll
    for (int s = 0; s < KSPLIT; ++s)
        acc += P[((size_t)s * NOUT + n) * BATCH + lane];
    out[(size_t)lane * NOUT + n] = acc;
}

// ---------------- spectral crop ----------------
__global__ __launch_bounds__(256) void spectral_kernel(
    const float* __restrict__ out)   // [BATCH][NOUT] slice just written
{
    __shared__ float sq[NG * NG];
    __shared__ float Pc[NG][MODES];
    __shared__ float Ps[NG][MODES];
    __shared__ float ct[NG], st[NG];

    const int b = blockIdx.x;
    const int tid = threadIdx.x;
    const float* o = out + (size_t)b * NOUT;

    for (int i = tid; i < NOUT; i += 256) sq[i] = o[i];
    if (tid < NG) { ct[tid] = g_ct[tid]; st[tid] = g_st[tid]; }
    __syncthreads();

    for (int i = tid; i < NG * MODES; i += 256) {
        int n1 = i / MODES, m2 = i % MODES;
        int k2 = (m2 + 34) % NG;
        float sc = 0.f, ss = 0.f;
        int idx = 0;
        #pragma unroll 1
        for (int n2 = 0; n2 < NG; ++n2) {
            float v = sq[n1 * NG + n2];
            sc += v * ct[idx];
            ss += v * st[idx];
            idx += k2; if (idx >= NG) idx -= NG;
        }
        Pc[n1][m2] = sc;
        Ps[n1][m2] = ss;
    }
    __syncthreads();

    for (int i = tid; i < MODES * MODES; i += 256) {
        int m1 = i / MODES, m2 = i % MODES;
        int k1 = (m1 + 34) % NG;
        float acc = 0.f;
        int idx = 0;
        #pragma unroll 1
        for (int n1 = 0; n1 < NG; ++n1) {
            acc += ct[idx] * Pc[n1][m2] - st[idx] * Ps[n1][m2];
            idx += k1; if (idx >= NG) idx -= NG;
        }
        g_x[(i >> 1) * 64 + 2 * b + (i & 1)] = acc;   // interleaved store
    }
}

// ---------------- driver ----------------
extern "C" void kernel_launch(void* const* d_in, const int* in_sizes, int n_in,
                              void* d_out, int out_size) {
    const float* x   = (const float*)d_in[0];
    const float* Wih = (const float*)d_in[1];
    const float* Whh = (const float*)d_in[2];
    const float* bih = (const float*)d_in[3];
    const float* bhh = (const float*)d_in[4];
    const float* fcw = (const float*)d_in[5];
    const float* fcb = (const float*)d_in[6];
    float* out = (float*)d_out;

    const int T = out_size / (BATCH * NOUT);

    float* hbase; cudaGetSymbolAddress((void**)&hbase, g_h);
    float* xbase; cudaGetSymbolAddress((void**)&xbase, g_x);
    float* pg;    cudaGetSymbolAddress((void**)&pg, g_pg);
    float* pf;    cudaGetSymbolAddress((void**)&pf, g_pf);

    const int GRID_GRU = (ROWS_GRU / RPB) * KSPLIT;            // 384
    const int GRID_FC  = ((NOUT + RPB - 1) / RPB) * KSPLIT;    // 160
    const int GRID_FCC = (NOUT + 7) / 8;                       // 313

    init_kernel<<<96, 256>>>(x);

    for (int t = 0; t < T; ++t) {
        const int p = t & 1, c = p ^ 1;
        const float* inp = xbase;
        for (int l = 0; l < NLAYERS; ++l) {
            const float* hp = hbase + ((size_t)p * NLAYERS + l) * HID * BATCH;
            float*       hc = hbase + ((size_t)c * NLAYERS + l) * HID * BATCH;
            gemm_partial_kernel<<<GRID_GRU, 256>>>(
                Wih + (size_t)l * GATES * HID,
                Whh + (size_t)l * GATES * HID,
                inp, hp, GATES, ROWS_GRU, pg);
            combine_gru_kernel<<<HID / 8, 256>>>(
                pg, bih + l * GATES, bhh + l * GATES, hp, hc);
            inp = hc;
        }
        float* oslice = out + (size_t)t * BATCH * NOUT;
        const float* hlast = hbase + ((size_t)c * NLAYERS + (NLAYERS - 1)) * HID * BATCH;
        gemm_partial_kernel<<<GRID_FC, 256>>>(
            fcw, fcw, hlast, hlast, NOUT, NOUT, pf);
        combine_fc_kernel<<<GRID_FCC, 256>>>(pf, fcb, oslice);
        spectral_kernel<<<BATCH, 256>>>(oslice);
    }
}

// round 6
// speedup vs baseline: 1.5893x; 1.5893x over previous
#include <cuda_runtime.h>
#include <math.h>

#define HID      1024
#define BATCH    32
#define NLAYERS  3
#define NOUT     2500
#define NG       50
#define MODES    32
#define GATES    3072
#define ROWS_GRU 6144
#define ROWS_FC  2560            // 2500 padded to 128 multiple
#define RPB      128             // rows per block (4 warps x 32 lanes)
#define KSPLIT   8
#define KSEG     (HID/KSPLIT)    // 128
#define NK4      (KSEG/4)        // 32

typedef unsigned long long ull;

// Activations stored [feature][batch] (row = 32 floats = 128B)
__device__ float g_h[2][NLAYERS][HID * BATCH];
__device__ float g_x[HID * BATCH];
__device__ float g_ct[NG];
__device__ float g_st[NG];
// Transposed weights: WT4[k4][row][4]  (4 k's packed per row per 16B)
__device__ float g_wtg[(size_t)NLAYERS * (HID / 4) * ROWS_GRU * 4];   // 75.5 MB
__device__ float g_wtf[(size_t)(HID / 4) * ROWS_FC * 4];              // 10.5 MB
// K-split partials
__device__ float g_pg[(size_t)KSPLIT * ROWS_GRU * BATCH];
__device__ float g_pf[(size_t)KSPLIT * ROWS_FC * BATCH];

// ---------------- packed fp32x2 helpers ----------------
__device__ __forceinline__ void ffma2(ull& acc, ull w, ull xh) {
    asm volatile("fma.rn.f32x2 %0, %1, %2, %0;" : "+l"(acc) : "l"(w), "l"(xh));
}
__device__ __forceinline__ ull dup2(float w) {
    ull r; unsigned u = __float_as_uint(w);
    asm("mov.b64 %0, {%1, %1};" : "=l"(r) : "r"(u));
    return r;
}
union F4U2 { float4 f4; ulonglong2 u2; };

// ---------------- cp.async ----------------
__device__ __forceinline__ void cp16(void* dst, const void* src) {
    unsigned d = (unsigned)__cvta_generic_to_shared(dst);
    asm volatile("cp.async.cg.shared.global [%0], [%1], 16;\n" :: "r"(d), "l"(src));
}
__device__ __forceinline__ void cp_commit() { asm volatile("cp.async.commit_group;\n"); }
template<int N> __device__ __forceinline__ void cp_wait() {
    asm volatile("cp.async.wait_group %0;\n" :: "n"(N));
}

// ---------------- init ----------------
__global__ void init_kernel(const float* __restrict__ x) {
    int tid = blockIdx.x * blockDim.x + threadIdx.x;
    int stride = gridDim.x * blockDim.x;
    float* h = (float*)g_h;
    int total = 2 * NLAYERS * HID * BATCH;
    for (int i = tid; i < total; i += stride) h[i] = 0.0f;
    for (int i = tid; i < HID * BATCH; i += stride) {
        int j = i >> 5, b = i & 31;
        g_x[j * BATCH + b] = x[b * HID + j];
    }
    if (tid < NG) {
        float ang = 6.283185307179586f * (float)tid / (float)NG;
        g_ct[tid] = cosf(ang);
        g_st[tid] = sinf(ang);
    }
}

// ---------------- weight transposes (once per launch) ----------------
__global__ void transpose_gru_kernel(const float* __restrict__ Wih,
                                     const float* __restrict__ Whh) {
    size_t total = (size_t)NLAYERS * (HID / 4) * ROWS_GRU * 4;
    size_t stride = (size_t)gridDim.x * blockDim.x;
    for (size_t d = (size_t)blockIdx.x * blockDim.x + threadIdx.x; d < total; d += stride) {
        int kl = (int)(d & 3);
        size_t t = d >> 2;
        int r  = (int)(t % ROWS_GRU); t /= ROWS_GRU;
        int k4 = (int)(t % (HID / 4));
        int l  = (int)(t / (HID / 4));
        int k = k4 * 4 + kl;
        float v = (r < GATES)
            ? Wih[((size_t)l * GATES + r) * HID + k]
            : Whh[((size_t)l * GATES + (r - GATES)) * HID + k];
        g_wtg[d] = v;
    }
}
__global__ void transpose_fc_kernel(const float* __restrict__ fcw) {
    size_t total = (size_t)(HID / 4) * ROWS_FC * 4;
    size_t stride = (size_t)gridDim.x * blockDim.x;
    for (size_t d = (size_t)blockIdx.x * blockDim.x + threadIdx.x; d < total; d += stride) {
        int kl = (int)(d & 3);
        size_t t = d >> 2;
        int r  = (int)(t % ROWS_FC);
        int k4 = (int)(t / ROWS_FC);
        int k = k4 * 4 + kl;
        g_wtf[d] = (r < NOUT) ? fcw[(size_t)r * HID + k] : 0.0f;
    }
}

// ---------------- partial GEMM ----------------
// P[ks][r][b] = sum_{k in seg ks} W[r][k] * act[k][b]
// lane = row (coalesced streaming weight LDG.128); activations broadcast
// from SMEM; thread holds all 32 batches as 16 f32x2 accumulators.
__global__ __launch_bounds__(128) void gemm_partial_kernel(
    const float4* __restrict__ WT,   // [NK4*KSPLIT][rows_total] float4
    const float* __restrict__ actA,  // rows in blocks < rowblocksA
    const float* __restrict__ actB,  // remaining rows
    int rowblocksA, int rows_total,
    float* __restrict__ P)
{
    __shared__ __align__(16) float Sp[KSEG][BATCH];   // 16 KB

    const int tid  = threadIdx.x;
    const int warp = tid >> 5;
    const int lane = tid & 31;
    const int rb = blockIdx.x / KSPLIT;
    const int ks = blockIdx.x % KSPLIT;
    const int r  = rb * RPB + warp * 32 + lane;

    const float* act = (rb < rowblocksA) ? actA : actB;
    const float* src = act + (size_t)ks * KSEG * BATCH;
    #pragma unroll
    for (int it = 0; it < 8; ++it) {
        int i = tid + it * 128;
        cp16((float*)Sp + i * 4, src + i * 4);
    }
    cp_commit(); cp_wait<0>();
    __syncthreads();

    ull acc[16];
    #pragma unroll
    for (int q = 0; q < 16; ++q) acc[q] = 0;

    const float4* wp = WT + (size_t)ks * NK4 * rows_total + r;
    float4 w0 = wp[0];
    float4 w1 = wp[rows_total];

    #pragma unroll 2
    for (int k4 = 0; k4 < NK4; ++k4) {
        float4 w2 = (k4 + 2 < NK4) ? wp[(size_t)(k4 + 2) * rows_total] : w0;
        ull wa = dup2(w0.x), wb = dup2(w0.y), wc = dup2(w0.z), wd = dup2(w0.w);
        const F4U2* a0 = (const F4U2*)&Sp[k4 * 4 + 0][0];
        const F4U2* a1 = (const F4U2*)&Sp[k4 * 4 + 1][0];
        const F4U2* a2 = (const F4U2*)&Sp[k4 * 4 + 2][0];
        const F4U2* a3 = (const F4U2*)&Sp[k4 * 4 + 3][0];
        #pragma unroll
        for (int p = 0; p < 8; ++p) {
            F4U2 v;
            v = a0[p]; ffma2(acc[2*p], wa, v.u2.x); ffma2(acc[2*p+1], wa, v.u2.y);
            v = a1[p]; ffma2(acc[2*p], wb, v.u2.x); ffma2(acc[2*p+1], wb, v.u2.y);
            v = a2[p]; ffma2(acc[2*p], wc, v.u2.x); ffma2(acc[2*p+1], wc, v.u2.y);
            v = a3[p]; ffma2(acc[2*p], wd, v.u2.x); ffma2(acc[2*p+1], wd, v.u2.y);
        }
        w0 = w1; w1 = w2;
    }

    ull* dst = (ull*)(P + ((size_t)ks * rows_total + r) * BATCH);
    #pragma unroll
    for (int q = 0; q < 16; ++q) dst[q] = acc[q];
}

// ---------------- GRU combine: K-reduce + nonlinearity ----------------
__global__ __launch_bounds__(256) void combine_gru_kernel(
    const float* __restrict__ P,
    const float* __restrict__ bih, const float* __restrict__ bhh,
    const float* __restrict__ hT, float* __restrict__ hnT)
{
    const int lane = threadIdx.x & 31;
    const int j    = blockIdx.x * 8 + (threadIdx.x >> 5);

    float s0 = 0.f, s1 = 0.f, s2 = 0.f, s3 = 0.f, s4 = 0.f, s5 = 0.f;
    #pragma unroll
    for (int ks = 0; ks < KSPLIT; ++ks) {
        const float* Ps = P + (size_t)ks * ROWS_GRU * BATCH;
        s0 += Ps[((size_t)(0 * HID + j)) * BATCH + lane];
        s1 += Ps[((size_t)(1 * HID + j)) * BATCH + lane];
        s2 += Ps[((size_t)(2 * HID + j)) * BATCH + lane];
        s3 += Ps[((size_t)(GATES + 0 * HID + j)) * BATCH + lane];
        s4 += Ps[((size_t)(GATES + 1 * HID + j)) * BATCH + lane];
        s5 += Ps[((size_t)(GATES + 2 * HID + j)) * BATCH + lane];
    }
    float ir  = s0 + bih[j];
    float iz  = s1 + bih[HID + j];
    float inn = s2 + bih[2 * HID + j];
    float hr  = s3 + bhh[j];
    float hz  = s4 + bhh[HID + j];
    float hn  = s5 + bhh[2 * HID + j];
    float rg = 1.0f / (1.0f + __expf(-(ir + hr)));
    float z  = 1.0f / (1.0f + __expf(-(iz + hz)));
    float n  = tanhf(inn + rg * hn);
    float hp = hT[(size_t)j * BATCH + lane];
    hnT[(size_t)j * BATCH + lane] = (1.0f - z) * n + z * hp;
}

// ---------------- FC combine ----------------
__global__ __launch_bounds__(256) void combine_fc_kernel(
    const float* __restrict__ P, const float* __restrict__ fcb,
    float* __restrict__ out)
{
    const int lane = threadIdx.x & 31;
    const int n    = blockIdx.x * 8 + (threadIdx.x >> 5);
    if (n >= NOUT) return;
    float acc = fcb[n];
    #pragma unroll
    for (int ks = 0; ks < KSPLIT; ++ks)
        acc += P[((size_t)ks * ROWS_FC + n) * BATCH + lane];
    out[(size_t)lane * NOUT + n] = acc;
}

// ---------------- spectral crop ----------------
__global__ __launch_bounds__(256) void spectral_kernel(
    const float* __restrict__ out)   // [BATCH][NOUT] slice just written
{
    __shared__ float sq[NG * NG];
    __shared__ float Pc[NG][MODES];
    __shared__ float Ps[NG][MODES];
    __shared__ float ct[NG], st[NG];

    const int b = blockIdx.x;
    const int tid = threadIdx.x;
    const float* o = out + (size_t)b * NOUT;

    for (int i = tid; i < NOUT; i += 256) sq[i] = o[i];
    if (tid < NG) { ct[tid] = g_ct[tid]; st[tid] = g_st[tid]; }
    __syncthreads();

    for (int i = tid; i < NG * MODES; i += 256) {
        int n1 = i / MODES, m2 = i % MODES;
        int k2 = (m2 + 34) % NG;
        float sc = 0.f, ss = 0.f;
        int idx = 0;
        #pragma unroll 1
        for (int n2 = 0; n2 < NG; ++n2) {
            float v = sq[n1 * NG + n2];
            sc += v * ct[idx];
            ss += v * st[idx];
            idx += k2; if (idx >= NG) idx -= NG;
        }
        Pc[n1][m2] = sc;
        Ps[n1][m2] = ss;
    }
    __syncthreads();

    for (int i = tid; i < MODES * MODES; i += 256) {
        int m1 = i / MODES, m2 = i % MODES;
        int k1 = (m1 + 34) % NG;
        float acc = 0.f;
        int idx = 0;
        #pragma unroll 1
        for (int n1 = 0; n1 < NG; ++n1) {
            acc += ct[idx] * Pc[n1][m2] - st[idx] * Ps[n1][m2];
            idx += k1; if (idx >= NG) idx -= NG;
        }
        g_x[(size_t)i * BATCH + b] = acc;
    }
}

// ---------------- driver ----------------
extern "C" void kernel_launch(void* const* d_in, const int* in_sizes, int n_in,
                              void* d_out, int out_size) {
    const float* x   = (const float*)d_in[0];
    const float* Wih = (const float*)d_in[1];
    const float* Whh = (const float*)d_in[2];
    const float* bih = (const float*)d_in[3];
    const float* bhh = (const float*)d_in[4];
    const float* fcw = (const float*)d_in[5];
    const float* fcb = (const float*)d_in[6];
    float* out = (float*)d_out;

    const int T = out_size / (BATCH * NOUT);

    float* hbase; cudaGetSymbolAddress((void**)&hbase, g_h);
    float* xbase; cudaGetSymbolAddress((void**)&xbase, g_x);
    float* wtg;   cudaGetSymbolAddress((void**)&wtg, g_wtg);
    float* wtf;   cudaGetSymbolAddress((void**)&wtf, g_wtf);
    float* pg;    cudaGetSymbolAddress((void**)&pg, g_pg);
    float* pf;    cudaGetSymbolAddress((void**)&pf, g_pf);

    const int GRID_GRU = (ROWS_GRU / RPB) * KSPLIT;   // 384
    const int GRID_FC  = (ROWS_FC  / RPB) * KSPLIT;   // 160
    const int GRID_FCC = (NOUT + 7) / 8;              // 313

    init_kernel<<<148, 256>>>(x);
    transpose_gru_kernel<<<1184, 256>>>(Wih, Whh);
    transpose_fc_kernel<<<592, 256>>>(fcw);

    for (int t = 0; t < T; ++t) {
        const int p = t & 1, c = p ^ 1;
        const float* inp = xbase;
        for (int l = 0; l < NLAYERS; ++l) {
            const float* hp = hbase + ((size_t)p * NLAYERS + l) * HID * BATCH;
            float*       hc = hbase + ((size_t)c * NLAYERS + l) * HID * BATCH;
            const float4* WT = (const float4*)wtg + (size_t)l * (HID / 4) * ROWS_GRU;
            gemm_partial_kernel<<<GRID_GRU, 128>>>(WT, inp, hp,
                                                   GATES / RPB, ROWS_GRU, pg);
            combine_gru_kernel<<<HID / 8, 256>>>(pg, bih + l * GATES,
                                                 bhh + l * GATES, hp, hc);
            inp = hc;
        }
        float* oslice = out + (size_t)t * BATCH * NOUT;
        const float* hlast = hbase + ((size_t)c * NLAYERS + (NLAYERS - 1)) * HID * BATCH;
        gemm_partial_kernel<<<GRID_FC, 128>>>((const float4*)wtf, hlast, hlast,
                                              ROWS_FC / RPB, ROWS_FC, pf);
        combine_fc_kernel<<<GRID_FCC, 256>>>(pf, fcb, oslice);
        spectral_kernel<<<BATCH, 256>>>(oslice);
    }
}

// round 8
// speedup vs baseline: 2.2717x; 1.4294x over previous
#include <cuda_runtime.h>
#include <cuda_bf16.h>
#include <math.h>
#include <stdint.h>

#define HID      1024
#define BATCH    32
#define NLAYERS  3
#define NOUT     2500
#define NG       50
#define MODES    32
#define GATES    3072
#define ROWS_GRU 6144
#define TILES_GRU (ROWS_GRU/16)     // 384
#define TILES_FC  160               // 2560 rows
#define ROWS_FC  (TILES_FC*16)
#define NS       64                 // k16 steps (K=1024)
#define PSTRIDE  40                 // padded u32 stride per pair-row in smem
#define SMEM_B   (2*512*PSTRIDE*4)  // 163840 bytes

typedef unsigned int u32;

// ---- persistent device scratch ----
// Weight blobs, fragment-major: per (tile,s): 64 uint4 = [hi:32 lanes][lo:32 lanes]
__device__ __align__(16) uint4 g_wg[(size_t)NLAYERS * TILES_GRU * NS * 64];  // 72 MB
__device__ __align__(16) uint4 g_wf[(size_t)TILES_FC * NS * 64];             // 10 MB
// Activation blobs: pair-words [512 pairs][2 (hi/lo)][32 batch] u32
__device__ u32 g_bx[512 * 64];
__device__ u32 g_bh[NLAYERS][512 * 64];
__device__ float g_G[ROWS_GRU * BATCH];          // fp32 gates
__device__ float g_hf[NLAYERS][HID * BATCH];     // fp32 h [j][b] (in-place update)
__device__ float g_ct[NG], g_st[NG];

// ---- helpers ----
__device__ __forceinline__ unsigned short f2bf(float v) {
    __nv_bfloat16 h = __float2bfloat16(v);
    return *reinterpret_cast<unsigned short*>(&h);
}
__device__ __forceinline__ float bf2f(unsigned short u) {
    __nv_bfloat16 h = *reinterpret_cast<__nv_bfloat16*>(&u);
    return __bfloat162float(h);
}
__device__ __forceinline__ u32 packbf(float a, float b) {
    return (u32)f2bf(a) | ((u32)f2bf(b) << 16);
}
__device__ __forceinline__ void cp16(void* dst, const void* src) {
    unsigned d = (unsigned)__cvta_generic_to_shared(dst);
    asm volatile("cp.async.cg.shared.global [%0], [%1], 16;\n" :: "r"(d), "l"(src));
}
__device__ __forceinline__ void cp_commit() { asm volatile("cp.async.commit_group;\n"); }
__device__ __forceinline__ void cp_wait0() { asm volatile("cp.async.wait_group 0;\n"); }

#define MMA(c, A, b0, b1)                                                     \
    asm volatile(                                                             \
        "mma.sync.aligned.m16n8k16.row.col.f32.bf16.bf16.f32 "                \
        "{%0,%1,%2,%3}, {%4,%5,%6,%7}, {%8,%9}, {%0,%1,%2,%3};"               \
        : "+f"((c)[0]), "+f"((c)[1]), "+f"((c)[2]), "+f"((c)[3])              \
        : "r"((A).x), "r"((A).y), "r"((A).z), "r"((A).w), "r"(b0), "r"(b1))

// ---- init: zero h fp32 + h blobs, build x blobs, trig ----
__global__ void init_kernel(const float* __restrict__ x) {
    int tid = blockIdx.x * blockDim.x + threadIdx.x;
    int stride = gridDim.x * blockDim.x;
    float* h = (float*)g_hf;
    for (int i = tid; i < NLAYERS * HID * BATCH; i += stride) h[i] = 0.0f;
    u32* bh = (u32*)g_bh;
    for (int i = tid; i < NLAYERS * 512 * 64; i += stride) bh[i] = 0u;
    for (int i = tid; i < HID * BATCH; i += stride) {
        int j = i >> 5, b = i & 31;
        float v = x[b * HID + j];
        unsigned short hi = f2bf(v);
        unsigned short lo = f2bf(v - bf2f(hi));
        int p = j >> 1, hf = j & 1;
        ((unsigned short*)g_bx)[(p * 64 + b) * 2 + hf] = hi;          // hi word block
        ((unsigned short*)g_bx)[(p * 64 + 32 + b) * 2 + hf] = lo;     // lo word block
    }
    if (tid < NG) {
        float ang = 6.283185307179586f * (float)tid / (float)NG;
        g_ct[tid] = cosf(ang);
        g_st[tid] = sinf(ang);
    }
}

// ---- prepack weights into mma-fragment-major hi/lo blobs ----
__device__ __forceinline__ void pack_frag(uint4* dst_hi, const float* r0p, const float* r1p) {
    // r0p/r1p point at W[rowA][k], W[rowB][k] (k..k+9 needed)
    float w00 = r0p[0], w01 = r0p[1], w20 = r0p[8], w21 = r0p[9];
    float w10 = r1p[0], w11 = r1p[1], w30 = r1p[8], w31 = r1p[9];
    uint4 hi, lo;
    hi.x = packbf(w00, w01); hi.y = packbf(w10, w11);
    hi.z = packbf(w20, w21); hi.w = packbf(w30, w31);
    lo.x = packbf(w00 - bf2f(f2bf(w00)), w01 - bf2f(f2bf(w01)));
    lo.y = packbf(w10 - bf2f(f2bf(w10)), w11 - bf2f(f2bf(w11)));
    lo.z = packbf(w20 - bf2f(f2bf(w20)), w21 - bf2f(f2bf(w21)));
    lo.w = packbf(w30 - bf2f(f2bf(w30)), w31 - bf2f(f2bf(w31)));
    dst_hi[0]  = hi;
    dst_hi[32] = lo;
}

__global__ void prepack_gru_kernel(const float* __restrict__ Wih,
                                   const float* __restrict__ Whh) {
    const int total = NLAYERS * TILES_GRU * NS * 32;
    int stride = gridDim.x * blockDim.x;
    for (int idx = blockIdx.x * blockDim.x + threadIdx.x; idx < total; idx += stride) {
        int lane = idx & 31;
        int s    = (idx >> 5) & (NS - 1);
        int t    = (idx >> 11) % TILES_GRU;
        int l    = (idx >> 11) / TILES_GRU;
        int g = lane >> 2, tig = lane & 3;
        int rA = t * 16 + g, rB = rA + 8;
        int k = s * 16 + 2 * tig;
        const float* WihL = Wih + (size_t)l * GATES * HID;
        const float* WhhL = Whh + (size_t)l * GATES * HID;
        const float* r0p = (rA < GATES) ? WihL + (size_t)rA * HID + k
                                        : WhhL + (size_t)(rA - GATES) * HID + k;
        const float* r1p = (rB < GATES) ? WihL + (size_t)rB * HID + k
                                        : WhhL + (size_t)(rB - GATES) * HID + k;
        uint4* dst = g_wg + ((size_t)(l * TILES_GRU + t) * NS + s) * 64 + lane;
        pack_frag(dst, r0p, r1p);
    }
}

__global__ void prepack_fc_kernel(const float* __restrict__ fcw) {
    const int total = TILES_FC * NS * 32;
    int stride = gridDim.x * blockDim.x;
    for (int idx = blockIdx.x * blockDim.x + threadIdx.x; idx < total; idx += stride) {
        int lane = idx & 31;
        int s    = (idx >> 5) & (NS - 1);
        int t    = (idx >> 11);
        int g = lane >> 2, tig = lane & 3;
        int rA = t * 16 + g, rB = rA + 8;
        int k = s * 16 + 2 * tig;
        float zbuf[10] = {0,0,0,0,0,0,0,0,0,0};
        const float* r0p = (rA < NOUT) ? fcw + (size_t)rA * HID + k : zbuf;
        const float* r1p = (rB < NOUT) ? fcw + (size_t)rB * HID + k : zbuf;
        uint4* dst = g_wf + ((size_t)t * NS + s) * 64 + lane;
        pack_frag(dst, r0p, r1p);
    }
}

// ---- GEMM core: stage B (pair-word blob) into padded smem, mma over K ----
__device__ __forceinline__ void stage_B(u32* Bs, const u32* __restrict__ Bglob, int tid) {
    #pragma unroll
    for (int it = 0; it < 64; ++it) {
        int i = tid + it * 128;
        int p = i >> 4, seg = i & 15;
        int hl = seg >> 3, ns = seg & 7;
        cp16(Bs + (hl * 512 + p) * PSTRIDE + ns * 4,
             Bglob + p * 64 + hl * 32 + ns * 4);
    }
    cp_commit(); cp_wait0();
}

__device__ __forceinline__ void gemm_tile(const uint4* __restrict__ wq,
                                          const u32* Bs, int g, int tig,
                                          float acc[4][4]) {
    uint4 ah = wq[0], al = wq[32];
    #pragma unroll 4
    for (int s = 0; s < NS; ++s) {
        uint4 ahn, aln;
        if (s + 1 < NS) { ahn = wq[(s + 1) * 64]; aln = wq[(s + 1) * 64 + 32]; }
        const int prh = s * 8 + tig;
        #pragma unroll
        for (int nt = 0; nt < 4; ++nt) {
            const int col = g + 8 * nt;
            u32 bh0 = Bs[prh * PSTRIDE + col];
            u32 bh1 = Bs[(prh + 4) * PSTRIDE + col];
            u32 bl0 = Bs[(512 + prh) * PSTRIDE + col];
            u32 bl1 = Bs[(512 + prh + 4) * PSTRIDE + col];
            MMA(acc[nt], ah, bh0, bh1);
            MMA(acc[nt], al, bh0, bh1);
            MMA(acc[nt], ah, bl0, bl1);
        }
        ah = ahn; al = aln;
    }
}

// ---- GRU gemm: 96 blocks x 4 warps; tile t = blockIdx*4+warp; B: x for t<192, h else
__global__ __launch_bounds__(128) void gemm_gru(
    const uint4* __restrict__ Wblob, const u32* __restrict__ Bx,
    const u32* __restrict__ Bh, float* __restrict__ G)
{
    extern __shared__ u32 Bs[];
    const int tid = threadIdx.x;
    const int warp = tid >> 5, lane = tid & 31;
    const int g = lane >> 2, tig = lane & 3;
    const int t = blockIdx.x * 4 + warp;

    stage_B(Bs, (blockIdx.x < 48) ? Bx : Bh, tid);
    __syncthreads();

    float acc[4][4] = {};
    gemm_tile(Wblob + (size_t)t * NS * 64 + lane, Bs, g, tig, acc);

    const int R = t * 16;
    #pragma unroll
    for (int nt = 0; nt < 4; ++nt) {
        int b0 = nt * 8 + 2 * tig;
        *(float2*)(G + (size_t)(R + g) * BATCH + b0)     = make_float2(acc[nt][0], acc[nt][1]);
        *(float2*)(G + (size_t)(R + g + 8) * BATCH + b0) = make_float2(acc[nt][2], acc[nt][3]);
    }
}

// ---- FC gemm: 40 blocks x 4 warps; fused bias + transposed store ----
__global__ __launch_bounds__(128) void gemm_fc(
    const uint4* __restrict__ Wblob, const u32* __restrict__ Bh,
    const float* __restrict__ fcb, float* __restrict__ out)
{
    extern __shared__ u32 Bs[];
    const int tid = threadIdx.x;
    const int warp = tid >> 5, lane = tid & 31;
    const int g = lane >> 2, tig = lane & 3;
    const int t = blockIdx.x * 4 + warp;

    stage_B(Bs, Bh, tid);
    __syncthreads();

    float acc[4][4] = {};
    gemm_tile(Wblob + (size_t)t * NS * 64 + lane, Bs, g, tig, acc);

    const int rA = t * 16 + g, rB = rA + 8;
    const float biasA = (rA < NOUT) ? fcb[rA] : 0.0f;
    const float biasB = (rB < NOUT) ? fcb[rB] : 0.0f;
    #pragma unroll
    for (int nt = 0; nt < 4; ++nt) {
        int b0 = nt * 8 + 2 * tig;
        if (rA < NOUT) {
            out[(size_t)b0 * NOUT + rA]       = acc[nt][0] + biasA;
            out[(size_t)(b0 + 1) * NOUT + rA] = acc[nt][1] + biasA;
        }
        if (rB < NOUT) {
            out[(size_t)b0 * NOUT + rB]       = acc[nt][2] + biasB;
            out[(size_t)(b0 + 1) * NOUT + rB] = acc[nt][3] + biasB;
        }
    }
}

// ---- GRU combine: gates -> h (fp32 in-place) + hi/lo blob ----
__global__ __launch_bounds__(256) void combine_gru_kernel(
    const float* __restrict__ G,
    const float* __restrict__ bih, const float* __restrict__ bhh,
    float* __restrict__ hf, u32* __restrict__ blob)
{
    const int lane = threadIdx.x & 31;
    const int j    = blockIdx.x * 8 + (threadIdx.x >> 5);
    float ir  = G[(size_t)(0 * HID + j) * BATCH + lane] + bih[j];
    float iz  = G[(size_t)(1 * HID + j) * BATCH + lane] + bih[HID + j];
    float inn = G[(size_t)(2 * HID + j) * BATCH + lane] + bih[2 * HID + j];
    float hr  = G[(size_t)(GATES + 0 * HID + j) * BATCH + lane] + bhh[j];
    float hz  = G[(size_t)(GATES + 1 * HID + j) * BATCH + lane] + bhh[HID + j];
    float hn  = G[(size_t)(GATES + 2 * HID + j) * BATCH + lane] + bhh[2 * HID + j];
    float r = 1.0f / (1.0f + __expf(-(ir + hr)));
    float z = 1.0f / (1.0f + __expf(-(iz + hz)));
    float n = tanhf(inn + r * hn);
    float hp = hf[(size_t)j * BATCH + lane];
    float h = (1.0f - z) * n + z * hp;
    hf[(size_t)j * BATCH + lane] = h;
    unsigned short hi = f2bf(h);
    unsigned short lo = f2bf(h - bf2f(hi));
    int p = j >> 1, half = j & 1;
    ((unsigned short*)blob)[(p * 64 + lane) * 2 + half] = hi;
    ((unsigned short*)blob)[(p * 64 + 32 + lane) * 2 + half] = lo;
}

// ---- spectral crop -> x blobs ----
__global__ __launch_bounds__(256) void spectral_kernel(const float* __restrict__ out)
{
    __shared__ float sq[NG * NG];
    __shared__ float Pc[NG][MODES];
    __shared__ float Ps[NG][MODES];
    __shared__ float ct[NG], st[NG];

    const int b = blockIdx.x;
    const int tid = threadIdx.x;
    const float* o = out + (size_t)b * NOUT;

    for (int i = tid; i < NOUT; i += 256) sq[i] = o[i];
    if (tid < NG) { ct[tid] = g_ct[tid]; st[tid] = g_st[tid]; }
    __syncthreads();

    for (int i = tid; i < NG * MODES; i += 256) {
        int n1 = i / MODES, m2 = i % MODES;
        int k2 = (m2 + 34) % NG;
        float sc = 0.f, ss = 0.f;
        int idx = 0;
        #pragma unroll 1
        for (int n2 = 0; n2 < NG; ++n2) {
            float v = sq[n1 * NG + n2];
            sc += v * ct[idx];
            ss += v * st[idx];
            idx += k2; if (idx >= NG) idx -= NG;
        }
        Pc[n1][m2] = sc;
        Ps[n1][m2] = ss;
    }
    __syncthreads();

    for (int i = tid; i < MODES * MODES; i += 256) {
        int m1 = i / MODES, m2 = i % MODES;
        int k1 = (m1 + 34) % NG;
        float acc = 0.f;
        int idx = 0;
        #pragma unroll 1
        for (int n1 = 0; n1 < NG; ++n1) {
            acc += ct[idx] * Pc[n1][m2] - st[idx] * Ps[n1][m2];
            idx += k1; if (idx >= NG) idx -= NG;
        }
        unsigned short hi = f2bf(acc);
        unsigned short lo = f2bf(acc - bf2f(hi));
        int p = i >> 1, half = i & 1;
        ((unsigned short*)g_bx)[(p * 64 + b) * 2 + half] = hi;
        ((unsigned short*)g_bx)[(p * 64 + 32 + b) * 2 + half] = lo;
    }
}

// ---- driver ----
extern "C" void kernel_launch(void* const* d_in, const int* in_sizes, int n_in,
                              void* d_out, int out_size) {
    const float* x   = (const float*)d_in[0];
    const float* Wih = (const float*)d_in[1];
    const float* Whh = (const float*)d_in[2];
    const float* bih = (const float*)d_in[3];
    const float* bhh = (const float*)d_in[4];
    const float* fcw = (const float*)d_in[5];
    const float* fcb = (const float*)d_in[6];
    float* out = (float*)d_out;

    const int T = out_size / (BATCH * NOUT);

    uint4* wg; cudaGetSymbolAddress((void**)&wg, g_wg);
    uint4* wf; cudaGetSymbolAddress((void**)&wf, g_wf);
    u32* bx;   cudaGetSymbolAddress((void**)&bx, g_bx);
    u32* bh;   cudaGetSymbolAddress((void**)&bh, g_bh);
    float* G;  cudaGetSymbolAddress((void**)&G, g_G);
    float* hf; cudaGetSymbolAddress((void**)&hf, g_hf);

    static int smem_set = 0;
    cudaFuncSetAttribute(gemm_gru, cudaFuncAttributeMaxDynamicSharedMemorySize, SMEM_B);
    cudaFuncSetAttribute(gemm_fc,  cudaFuncAttributeMaxDynamicSharedMemorySize, SMEM_B);
    (void)smem_set;

    init_kernel<<<148, 256>>>(x);
    prepack_gru_kernel<<<2048, 256>>>(Wih, Whh);
    prepack_fc_kernel<<<1280, 256>>>(fcw);

    for (int t = 0; t < T; ++t) {
        const u32* inp = bx;
        for (int l = 0; l < NLAYERS; ++l) {
            u32* bhl = bh + (size_t)l * 512 * 64;
            gemm_gru<<<96, 128, SMEM_B>>>(
                wg + (size_t)l * TILES_GRU * NS * 64, inp, bhl, G);
            combine_gru_kernel<<<HID / 8, 256>>>(G, bih + l * GATES, bhh + l * GATES,
                                                 hf + (size_t)l * HID * BATCH, bhl);
            inp = bhl;
        }
        float* oslice = out + (size_t)t * BATCH * NOUT;
        gemm_fc<<<40, 128, SMEM_B>>>(wf, bh + (size_t)(NLAYERS - 1) * 512 * 64,
                                     fcb, oslice);
        spectral_kernel<<<BATCH, 256>>>(oslice);
    }
}

// round 9
// speedup vs baseline: 2.9641x; 1.3048x over previous
#include <cuda_runtime.h>
#include <cuda_bf16.h>
#include <math.h>
#include <stdint.h>

#define HID      1024
#define BATCH    32
#define NLAYERS  3
#define NOUT     2500
#define NG       50
#define MODES    32
#define GATES    3072
#define ROWS_GRU 6144
#define TILES_GRU (ROWS_GRU/16)     // 384
#define TILES_FC  160               // 2560 rows
#define ROWS_FC  (TILES_FC*16)
#define NS       64                 // k16 steps (K=1024)
#define KSPLIT   4
#define SSEG     (NS/KSPLIT)        // 16 k16-steps per job
#define PSEG     (SSEG*8)           // 128 pair-rows per segment
#define PSTRIDE  40                 // padded u32 stride per pair-row in smem
#define SMEM_SEG (2*PSEG*PSTRIDE*4) // 40960 bytes

typedef unsigned int u32;

// ---- persistent device scratch ----
__device__ __align__(16) uint4 g_wg[(size_t)NLAYERS * TILES_GRU * NS * 64];  // 72 MB
__device__ __align__(16) uint4 g_wf[(size_t)TILES_FC * NS * 64];             // 10 MB
// Activation blobs: [512 pairs][hi:32 | lo:32] u32
__device__ u32 g_bx[512 * 64];
__device__ u32 g_bh[NLAYERS][512 * 64];
__device__ float g_P [KSPLIT][ROWS_GRU * BATCH];   // GRU K-split partials (3.1 MB)
__device__ float g_Pf[KSPLIT][ROWS_FC * BATCH];    // FC partials (1.3 MB)
__device__ float g_hf[NLAYERS][HID * BATCH];       // fp32 h [j][b]
__device__ float g_ct[NG], g_st[NG];

// ---- helpers ----
__device__ __forceinline__ unsigned short f2bf(float v) {
    __nv_bfloat16 h = __float2bfloat16(v);
    return *reinterpret_cast<unsigned short*>(&h);
}
__device__ __forceinline__ float bf2f(unsigned short u) {
    __nv_bfloat16 h = *reinterpret_cast<__nv_bfloat16*>(&u);
    return __bfloat162float(h);
}
__device__ __forceinline__ u32 packbf(float a, float b) {
    return (u32)f2bf(a) | ((u32)f2bf(b) << 16);
}
__device__ __forceinline__ void cp16(void* dst, const void* src) {
    unsigned d = (unsigned)__cvta_generic_to_shared(dst);
    asm volatile("cp.async.cg.shared.global [%0], [%1], 16;\n" :: "r"(d), "l"(src));
}
__device__ __forceinline__ void cp_commit() { asm volatile("cp.async.commit_group;\n"); }
__device__ __forceinline__ void cp_wait0() { asm volatile("cp.async.wait_group 0;\n"); }

#define MMA(c, A, b0, b1)                                                     \
    asm volatile(                                                             \
        "mma.sync.aligned.m16n8k16.row.col.f32.bf16.bf16.f32 "                \
        "{%0,%1,%2,%3}, {%4,%5,%6,%7}, {%8,%9}, {%0,%1,%2,%3};"               \
        : "+f"((c)[0]), "+f"((c)[1]), "+f"((c)[2]), "+f"((c)[3])              \
        : "r"((A).x), "r"((A).y), "r"((A).z), "r"((A).w), "r"(b0), "r"(b1))

// ---- init ----
__global__ void init_kernel(const float* __restrict__ x) {
    int tid = blockIdx.x * blockDim.x + threadIdx.x;
    int stride = gridDim.x * blockDim.x;
    float* h = (float*)g_hf;
    for (int i = tid; i < NLAYERS * HID * BATCH; i += stride) h[i] = 0.0f;
    u32* bh = (u32*)g_bh;
    for (int i = tid; i < NLAYERS * 512 * 64; i += stride) bh[i] = 0u;
    for (int i = tid; i < HID * BATCH; i += stride) {
        int j = i >> 5, b = i & 31;
        float v = x[b * HID + j];
        unsigned short hi = f2bf(v);
        unsigned short lo = f2bf(v - bf2f(hi));
        int p = j >> 1, hf = j & 1;
        ((unsigned short*)g_bx)[(p * 64 + b) * 2 + hf] = hi;
        ((unsigned short*)g_bx)[(p * 64 + 32 + b) * 2 + hf] = lo;
    }
    if (tid < NG) {
        float ang = 6.283185307179586f * (float)tid / (float)NG;
        g_ct[tid] = cosf(ang);
        g_st[tid] = sinf(ang);
    }
}

// ---- prepack ----
__device__ __forceinline__ void pack_frag(uint4* dst_hi, const float* r0p, const float* r1p) {
    float w00 = r0p[0], w01 = r0p[1], w20 = r0p[8], w21 = r0p[9];
    float w10 = r1p[0], w11 = r1p[1], w30 = r1p[8], w31 = r1p[9];
    uint4 hi, lo;
    hi.x = packbf(w00, w01); hi.y = packbf(w10, w11);
    hi.z = packbf(w20, w21); hi.w = packbf(w30, w31);
    lo.x = packbf(w00 - bf2f(f2bf(w00)), w01 - bf2f(f2bf(w01)));
    lo.y = packbf(w10 - bf2f(f2bf(w10)), w11 - bf2f(f2bf(w11)));
    lo.z = packbf(w20 - bf2f(f2bf(w20)), w21 - bf2f(f2bf(w21)));
    lo.w = packbf(w30 - bf2f(f2bf(w30)), w31 - bf2f(f2bf(w31)));
    dst_hi[0]  = hi;
    dst_hi[32] = lo;
}

__global__ void prepack_gru_kernel(const float* __restrict__ Wih,
                                   const float* __restrict__ Whh) {
    const int total = NLAYERS * TILES_GRU * NS * 32;
    int stride = gridDim.x * blockDim.x;
    for (int idx = blockIdx.x * blockDim.x + threadIdx.x; idx < total; idx += stride) {
        int lane = idx & 31;
        int s    = (idx >> 5) & (NS - 1);
        int t    = (idx >> 11) % TILES_GRU;
        int l    = (idx >> 11) / TILES_GRU;
        int g = lane >> 2, tig = lane & 3;
        int rA = t * 16 + g, rB = rA + 8;
        int k = s * 16 + 2 * tig;
        const float* WihL = Wih + (size_t)l * GATES * HID;
        const float* WhhL = Whh + (size_t)l * GATES * HID;
        const float* r0p = (rA < GATES) ? WihL + (size_t)rA * HID + k
                                        : WhhL + (size_t)(rA - GATES) * HID + k;
        const float* r1p = (rB < GATES) ? WihL + (size_t)rB * HID + k
                                        : WhhL + (size_t)(rB - GATES) * HID + k;
        pack_frag(g_wg + ((size_t)(l * TILES_GRU + t) * NS + s) * 64 + lane, r0p, r1p);
    }
}

__global__ void prepack_fc_kernel(const float* __restrict__ fcw) {
    const int total = TILES_FC * NS * 32;
    int stride = gridDim.x * blockDim.x;
    for (int idx = blockIdx.x * blockDim.x + threadIdx.x; idx < total; idx += stride) {
        int lane = idx & 31;
        int s    = (idx >> 5) & (NS - 1);
        int t    = (idx >> 11);
        int g = lane >> 2, tig = lane & 3;
        int rA = t * 16 + g, rB = rA + 8;
        int k = s * 16 + 2 * tig;
        float zbuf[10] = {0,0,0,0,0,0,0,0,0,0};
        const float* r0p = (rA < NOUT) ? fcw + (size_t)rA * HID + k : zbuf;
        const float* r1p = (rB < NOUT) ? fcw + (size_t)rB * HID + k : zbuf;
        pack_frag(g_wf + ((size_t)t * NS + s) * 64 + lane, r0p, r1p);
    }
}

// ---- stage one K-segment of B into padded smem (256 threads) ----
__device__ __forceinline__ void stage_B(u32* Bs, const u32* __restrict__ Bglob,
                                        int ks, int tid) {
    const u32* src = Bglob + (size_t)ks * PSEG * 64;
    #pragma unroll
    for (int it = 0; it < 8; ++it) {
        int i = tid + it * 256;                 // 2048 cp16 total
        int p = i >> 4, seg = i & 15;
        int hl = seg >> 3, ns = seg & 7;
        cp16(Bs + ((hl * PSEG + p) * PSTRIDE) + ns * 4,
             src + p * 64 + hl * 32 + ns * 4);
    }
    cp_commit(); cp_wait0();
}

// ---- per-warp tile x K-segment: 16 steps, 4 MMA passes ----
__device__ __forceinline__ void gemm_tile(const uint4* __restrict__ wq,
                                          const u32* Bs, int g, int tig,
                                          float acc[4][4]) {
    uint4 ah = wq[0], al = wq[32];
    #pragma unroll
    for (int s = 0; s < SSEG; ++s) {
        int sn = (s + 1 < SSEG) ? s + 1 : s;
        uint4 ahn = wq[sn * 64], aln = wq[sn * 64 + 32];
        const int prh = s * 8 + tig;
        #pragma unroll
        for (int nt = 0; nt < 4; ++nt) {
            const int col = g + 8 * nt;
            u32 bh0 = Bs[prh * PSTRIDE + col];
            u32 bh1 = Bs[(prh + 4) * PSTRIDE + col];
            u32 bl0 = Bs[(PSEG + prh) * PSTRIDE + col];
            u32 bl1 = Bs[(PSEG + prh + 4) * PSTRIDE + col];
            MMA(acc[nt], ah, bh0, bh1);
            MMA(acc[nt], al, bh0, bh1);
            MMA(acc[nt], ah, bl0, bl1);
            MMA(acc[nt], al, bl0, bl1);
        }
        ah = ahn; al = aln;
    }
}

// ---- GRU gemm: grid = 48 tile-groups x KSPLIT; block = 256 (8 warps = 8 tiles)
__global__ __launch_bounds__(256) void gemm_gru(
    const uint4* __restrict__ Wblob, const u32* __restrict__ Bx,
    const u32* __restrict__ Bh, float* __restrict__ P)
{
    extern __shared__ u32 Bs[];
    const int tid = threadIdx.x;
    const int warp = tid >> 5, lane = tid & 31;
    const int g = lane >> 2, tig = lane & 3;
    const int tg = blockIdx.x >> 2;          // 0..47
    const int ks = blockIdx.x & 3;
    const int t  = tg * 8 + warp;

    stage_B(Bs, (tg < 24) ? Bx : Bh, ks, tid);
    __syncthreads();

    float acc[4][4] = {};
    gemm_tile(Wblob + ((size_t)t * NS + ks * SSEG) * 64 + lane, Bs, g, tig, acc);

    float* Pk = P + (size_t)ks * ROWS_GRU * BATCH;
    const int R = t * 16;
    #pragma unroll
    for (int nt = 0; nt < 4; ++nt) {
        int b0 = nt * 8 + 2 * tig;
        *(float2*)(Pk + (size_t)(R + g) * BATCH + b0)     = make_float2(acc[nt][0], acc[nt][1]);
        *(float2*)(Pk + (size_t)(R + g + 8) * BATCH + b0) = make_float2(acc[nt][2], acc[nt][3]);
    }
}

// ---- FC gemm: grid = 20 tile-groups x KSPLIT ----
__global__ __launch_bounds__(256) void gemm_fc(
    const uint4* __restrict__ Wblob, const u32* __restrict__ Bh,
    float* __restrict__ P)
{
    extern __shared__ u32 Bs[];
    const int tid = threadIdx.x;
    const int warp = tid >> 5, lane = tid & 31;
    const int g = lane >> 2, tig = lane & 3;
    const int tg = blockIdx.x >> 2;          // 0..19
    const int ks = blockIdx.x & 3;
    const int t  = tg * 8 + warp;

    stage_B(Bs, Bh, ks, tid);
    __syncthreads();

    float acc[4][4] = {};
    gemm_tile(Wblob + ((size_t)t * NS + ks * SSEG) * 64 + lane, Bs, g, tig, acc);

    float* Pk = P + (size_t)ks * ROWS_FC * BATCH;
    const int R = t * 16;
    #pragma unroll
    for (int nt = 0; nt < 4; ++nt) {
        int b0 = nt * 8 + 2 * tig;
        *(float2*)(Pk + (size_t)(R + g) * BATCH + b0)     = make_float2(acc[nt][0], acc[nt][1]);
        *(float2*)(Pk + (size_t)(R + g + 8) * BATCH + b0) = make_float2(acc[nt][2], acc[nt][3]);
    }
}

// ---- GRU combine: K-reduce partials -> gates -> h (fp32 + blob) ----
__global__ __launch_bounds__(256) void combine_gru_kernel(
    const float* __restrict__ P,
    const float* __restrict__ bih, const float* __restrict__ bhh,
    float* __restrict__ hf, u32* __restrict__ blob)
{
    const int lane = threadIdx.x & 31;
    const int j    = blockIdx.x * 8 + (threadIdx.x >> 5);
    float ir  = bih[j],           iz = bih[HID + j],  inn = bih[2 * HID + j];
    float hr  = bhh[j],           hz = bhh[HID + j],  hn  = bhh[2 * HID + j];
    #pragma unroll
    for (int ks = 0; ks < KSPLIT; ++ks) {
        const float* Pk = P + (size_t)ks * ROWS_GRU * BATCH;
        ir  += Pk[(size_t)(0 * HID + j) * BATCH + lane];
        iz  += Pk[(size_t)(1 * HID + j) * BATCH + lane];
        inn += Pk[(size_t)(2 * HID + j) * BATCH + lane];
        hr  += Pk[(size_t)(GATES + 0 * HID + j) * BATCH + lane];
        hz  += Pk[(size_t)(GATES + 1 * HID + j) * BATCH + lane];
        hn  += Pk[(size_t)(GATES + 2 * HID + j) * BATCH + lane];
    }
    float r = 1.0f / (1.0f + __expf(-(ir + hr)));
    float z = 1.0f / (1.0f + __expf(-(iz + hz)));
    float n = tanhf(inn + r * hn);
    float hp = hf[(size_t)j * BATCH + lane];
    float h = (1.0f - z) * n + z * hp;
    hf[(size_t)j * BATCH + lane] = h;
    unsigned short hi = f2bf(h);
    unsigned short lo = f2bf(h - bf2f(hi));
    int p = j >> 1, half = j & 1;
    ((unsigned short*)blob)[(p * 64 + lane) * 2 + half] = hi;
    ((unsigned short*)blob)[(p * 64 + 32 + lane) * 2 + half] = lo;
}

// ---- FC combine: K-reduce + bias + transposed store ----
__global__ __launch_bounds__(256) void combine_fc_kernel(
    const float* __restrict__ P, const float* __restrict__ fcb,
    float* __restrict__ out)
{
    const int lane = threadIdx.x & 31;
    const int n    = blockIdx.x * 8 + (threadIdx.x >> 5);
    if (n >= NOUT) return;
    float acc = fcb[n];
    #pragma unroll
    for (int ks = 0; ks < KSPLIT; ++ks)
        acc += P[(size_t)ks * ROWS_FC * BATCH + (size_t)n * BATCH + lane];
    out[(size_t)lane * NOUT + n] = acc;
}

// ---- spectral crop -> x blobs ----
__global__ __launch_bounds__(256) void spectral_kernel(const float* __restrict__ out)
{
    __shared__ float sq[NG * NG];
    __shared__ float Pc[NG][MODES];
    __shared__ float Ps[NG][MODES];
    __shared__ float ct[NG], st[NG];

    const int b = blockIdx.x;
    const int tid = threadIdx.x;
    const float* o = out + (size_t)b * NOUT;

    for (int i = tid; i < NOUT; i += 256) sq[i] = o[i];
    if (tid < NG) { ct[tid] = g_ct[tid]; st[tid] = g_st[tid]; }
    __syncthreads();

    for (int i = tid; i < NG * MODES; i += 256) {
        int n1 = i / MODES, m2 = i % MODES;
        int k2 = (m2 + 34) % NG;
        float sc = 0.f, ss = 0.f;
        int idx = 0;
        #pragma unroll 1
        for (int n2 = 0; n2 < NG; ++n2) {
            float v = sq[n1 * NG + n2];
            sc += v * ct[idx];
            ss += v * st[idx];
            idx += k2; if (idx >= NG) idx -= NG;
        }
        Pc[n1][m2] = sc;
        Ps[n1][m2] = ss;
    }
    __syncthreads();

    for (int i = tid; i < MODES * MODES; i += 256) {
        int m1 = i / MODES, m2 = i % MODES;
        int k1 = (m1 + 34) % NG;
        float acc = 0.f;
        int idx = 0;
        #pragma unroll 1
        for (int n1 = 0; n1 < NG; ++n1) {
            acc += ct[idx] * Pc[n1][m2] - st[idx] * Ps[n1][m2];
            idx += k1; if (idx >= NG) idx -= NG;
        }
        unsigned short hi = f2bf(acc);
        unsigned short lo = f2bf(acc - bf2f(hi));
        int p = i >> 1, half = i & 1;
        ((unsigned short*)g_bx)[(p * 64 + b) * 2 + half] = hi;
        ((unsigned short*)g_bx)[(p * 64 + 32 + b) * 2 + half] = lo;
    }
}

// ---- driver ----
extern "C" void kernel_launch(void* const* d_in, const int* in_sizes, int n_in,
                              void* d_out, int out_size) {
    const float* x   = (const float*)d_in[0];
    const float* Wih = (const float*)d_in[1];
    const float* Whh = (const float*)d_in[2];
    const float* bih = (const float*)d_in[3];
    const float* bhh = (const float*)d_in[4];
    const float* fcw = (const float*)d_in[5];
    const float* fcb = (const float*)d_in[6];
    float* out = (float*)d_out;

    const int T = out_size / (BATCH * NOUT);

    uint4* wg; cudaGetSymbolAddress((void**)&wg, g_wg);
    uint4* wf; cudaGetSymbolAddress((void**)&wf, g_wf);
    u32* bx;   cudaGetSymbolAddress((void**)&bx, g_bx);
    u32* bh;   cudaGetSymbolAddress((void**)&bh, g_bh);
    float* P;  cudaGetSymbolAddress((void**)&P, g_P);
    float* Pf; cudaGetSymbolAddress((void**)&Pf, g_Pf);
    float* hf; cudaGetSymbolAddress((void**)&hf, g_hf);

    init_kernel<<<148, 256>>>(x);
    prepack_gru_kernel<<<2048, 256>>>(Wih, Whh);
    prepack_fc_kernel<<<1280, 256>>>(fcw);

    for (int t = 0; t < T; ++t) {
        const u32* inp = bx;
        for (int l = 0; l < NLAYERS; ++l) {
            u32* bhl = bh + (size_t)l * 512 * 64;
            gemm_gru<<<48 * KSPLIT, 256, SMEM_SEG>>>(
                wg + (size_t)l * TILES_GRU * NS * 64, inp, bhl, P);
            combine_gru_kernel<<<HID / 8, 256>>>(P, bih + l * GATES, bhh + l * GATES,
                                                 hf + (size_t)l * HID * BATCH, bhl);
            inp = bhl;
        }
        float* oslice = out + (size_t)t * BATCH * NOUT;
        gemm_fc<<<20 * KSPLIT, 256, SMEM_SEG>>>(
            wf, bh + (size_t)(NLAYERS - 1) * 512 * 64, Pf);
        combine_fc_kernel<<<(NOUT + 7) / 8, 256>>>(Pf, fcb, oslice);
        spectral_kernel<<<BATCH, 256>>>(oslice);
    }
}